// round 2
// baseline (speedup 1.0000x reference)
#include <cuda_runtime.h>
#include <math.h>

#define Bn 16
#define Hn 512
#define Wn 512
#define C1 16
#define C2 18
#define TW 32
#define TH 32          // tile height; 512 threads -> 2 rows per thread
#define HALO 34        // TH+2 (= TW+2)

// 256 MB scratch for conv1 output (B, C1, H, W)
__device__ float g_feat[(size_t)Bn * C1 * Hn * Wn];

// ---------------------------------------------------------------------------
// Kernel 1: conv1 (3->16, 3x3, pad 1) + bias + exact GELU -> g_feat
// Each thread computes a vertical pair of pixels (shares 2 of 4 input rows).
// ---------------------------------------------------------------------------
__global__ void conv1_gelu_kernel(const float* __restrict__ wind,
                                  const float* __restrict__ topo,
                                  const float* __restrict__ w1,
                                  const float* __restrict__ b1) {
    __shared__ float ws[C1 * 27];
    __shared__ float bs[C1];
    int tid = threadIdx.x;
    for (int i = tid; i < C1 * 27; i += blockDim.x) ws[i] = w1[i];
    if (tid < C1) bs[tid] = b1[tid];
    __syncthreads();

    int idx = blockIdx.x * blockDim.x + tid;      // [0, B*(H/2)*W)
    int x  = idx % Wn;
    int r  = idx / Wn;
    int y0 = (r % (Hn / 2)) * 2;
    int b  = r / (Hn / 2);

    const float* ch0 = wind + ((size_t)b * 2 + 0) * Hn * Wn;
    const float* ch1 = wind + ((size_t)b * 2 + 1) * Hn * Wn;
    const float* ch2 = topo + (size_t)b * Hn * Wn;
    const float* chp[3] = {ch0, ch1, ch2};

    // input rows y0-1 .. y0+2, cols x-1 .. x+1, 3 channels
    float in[3][4][3];
    #pragma unroll
    for (int i = 0; i < 3; i++) {
        #pragma unroll
        for (int yy = 0; yy < 4; yy++) {
            int gy = y0 - 1 + yy;
            #pragma unroll
            for (int xx = 0; xx < 3; xx++) {
                int gx = x - 1 + xx;
                float v = 0.0f;
                if (gy >= 0 && gy < Hn && gx >= 0 && gx < Wn)
                    v = __ldg(chp[i] + gy * Wn + gx);
                in[i][yy][xx] = v;
            }
        }
    }

    const float inv_sqrt2 = 0.70710678118654752440f;
    #pragma unroll
    for (int oc = 0; oc < C1; oc++) {
        float a0 = bs[oc], a1 = a0;
        #pragma unroll
        for (int i = 0; i < 3; i++) {
            #pragma unroll
            for (int ky = 0; ky < 3; ky++) {
                #pragma unroll
                for (int kx = 0; kx < 3; kx++) {
                    float w = ws[(oc * 3 + i) * 9 + ky * 3 + kx];
                    a0 = fmaf(w, in[i][ky][kx],     a0);
                    a1 = fmaf(w, in[i][ky + 1][kx], a1);
                }
            }
        }
        a0 = 0.5f * a0 * (1.0f + erff(a0 * inv_sqrt2));
        a1 = 0.5f * a1 * (1.0f + erff(a1 * inv_sqrt2));
        size_t base = (((size_t)b * C1 + oc) * Hn + y0) * Wn + x;
        g_feat[base]      = a0;
        g_feat[base + Wn] = a1;
    }
}

// ---------------------------------------------------------------------------
// Kernel 2 (fused): conv2 (16->18, 3x3, pad 1) + bias -> offsets in registers,
// then deformable bilinear sampling of pm25 with the 9-tap weight.
// Tile: 32x32 output pixels, 512 threads, 2 rows per thread.
// ---------------------------------------------------------------------------
__device__ __forceinline__ float samp_point(const float* __restrict__ img,
                                            int yi, int xi) {
    bool valid = (yi >= 0) & (yi < Hn) & (xi >= 0) & (xi < Wn);
    int yc = min(max(yi, 0), Hn - 1);
    int xc = min(max(xi, 0), Wn - 1);
    float v = __ldg(img + yc * Wn + xc);
    return valid ? v : 0.0f;
}

__device__ __forceinline__ float bilinear(const float* __restrict__ img,
                                          float py, float px) {
    float fy = floorf(py), fx = floorf(px);
    float wy = py - fy,    wx = px - fx;
    int yi = (int)fy,      xi = (int)fx;
    float v00 = samp_point(img, yi,     xi);
    float v01 = samp_point(img, yi,     xi + 1);
    float v10 = samp_point(img, yi + 1, xi);
    float v11 = samp_point(img, yi + 1, xi + 1);
    float omy = 1.0f - wy, omx = 1.0f - wx;
    return v00 * omy * omx + v01 * omy * wx + v10 * wy * omx + v11 * wy * wx;
}

__global__ void conv2_sample_kernel(const float* __restrict__ pm25,
                                    const float* __restrict__ w2,
                                    const float* __restrict__ b2,
                                    const float* __restrict__ wk,
                                    float* __restrict__ out) {
    extern __shared__ float smem[];
    float* sfeat = smem;                          // C1 * 34 * 34
    float* sw2   = sfeat + C1 * HALO * HALO;      // C2 * 144
    float* sb2   = sw2 + C2 * 144;                // C2
    float* swk   = sb2 + C2;                      // 9

    int tid = threadIdx.x;                        // 512
    int bx0 = blockIdx.x * TW;
    int by0 = blockIdx.y * TH;
    int b   = blockIdx.z;

    // ---- load feat tile (with zero halo) ----
    const int PLANE = HALO * HALO;                // 1156
    for (int i = tid; i < C1 * PLANE; i += 512) {
        int c   = i / PLANE;
        int rem = i - c * PLANE;
        int yy  = rem / HALO;
        int xx  = rem - yy * HALO;
        int gy = by0 + yy - 1;
        int gx = bx0 + xx - 1;
        float v = 0.0f;
        if (gy >= 0 && gy < Hn && gx >= 0 && gx < Wn)
            v = g_feat[(((size_t)b * C1 + c) * Hn + gy) * Wn + gx];
        sfeat[i] = v;
    }
    for (int i = tid; i < C2 * 144; i += 512) sw2[i] = w2[i];
    if (tid < C2) sb2[tid] = b2[tid];
    if (tid < 9)  swk[tid] = wk[tid];
    __syncthreads();

    int tx  = tid & 31;
    int tyA = tid >> 5;                           // 0..15; rows tyA, tyA+16

    float acc0[C2], acc1[C2];
    #pragma unroll
    for (int oc = 0; oc < C2; oc++) { acc0[oc] = sb2[oc]; acc1[oc] = sb2[oc]; }

    #pragma unroll 1
    for (int c = 0; c < C1; c++) {
        const float* fp = sfeat + c * PLANE;
        float f0[9], f1[9];
        #pragma unroll
        for (int ky = 0; ky < 3; ky++) {
            #pragma unroll
            for (int kx = 0; kx < 3; kx++) {
                f0[ky * 3 + kx] = fp[(tyA + ky)      * HALO + tx + kx];
                f1[ky * 3 + kx] = fp[(tyA + 16 + ky) * HALO + tx + kx];
            }
        }
        const float* wp = sw2 + c * 9;
        #pragma unroll
        for (int oc = 0; oc < C2; oc++) {
            #pragma unroll
            for (int t = 0; t < 9; t++) {
                float w = wp[oc * 144 + t];
                acc0[oc] = fmaf(w, f0[t], acc0[oc]);
                acc1[oc] = fmaf(w, f1[t], acc1[oc]);
            }
        }
    }

    // ---- deformable sampling ----
    const float* img = pm25 + (size_t)b * Hn * Wn;
    int x  = bx0 + tx;
    int ya = by0 + tyA;
    int yb = ya + 16;

    float oA = 0.0f, oB = 0.0f;
    #pragma unroll
    for (int k = 0; k < 9; k++) {
        float wkv = swk[k];
        if (wkv != 0.0f) {
            float kdy = (float)(k / 3 - 1);
            float kdx = (float)(k % 3 - 1);
            {
                float py = (float)ya + kdy + acc0[2 * k];
                float px = (float)x  + kdx + acc0[2 * k + 1];
                oA = fmaf(wkv, bilinear(img, py, px), oA);
            }
            {
                float py = (float)yb + kdy + acc1[2 * k];
                float px = (float)x  + kdx + acc1[2 * k + 1];
                oB = fmaf(wkv, bilinear(img, py, px), oB);
            }
        }
    }
    out[((size_t)b * Hn + ya) * Wn + x] = oA;
    out[((size_t)b * Hn + yb) * Wn + x] = oB;
}

// ---------------------------------------------------------------------------
extern "C" void kernel_launch(void* const* d_in, const int* in_sizes, int n_in,
                              void* d_out, int out_size) {
    const float* pm25 = (const float*)d_in[0];
    const float* wind = (const float*)d_in[1];
    const float* topo = (const float*)d_in[2];
    const float* w1   = (const float*)d_in[3];
    const float* b1   = (const float*)d_in[4];
    const float* w2   = (const float*)d_in[5];
    const float* b2   = (const float*)d_in[6];
    const float* wk   = (const float*)d_in[7];
    float* out = (float*)d_out;

    // Kernel 1: conv1 + GELU
    int n1 = Bn * (Hn / 2) * Wn;                  // 2,097,152 threads
    conv1_gelu_kernel<<<n1 / 256, 256>>>(wind, topo, w1, b1);

    // Kernel 2: fused conv2 + sampling
    int smemB = (C1 * HALO * HALO + C2 * 144 + C2 + 9) * (int)sizeof(float);
    cudaFuncSetAttribute(conv2_sample_kernel,
                         cudaFuncAttributeMaxDynamicSharedMemorySize, smemB);
    dim3 grid(Wn / TW, Hn / TH, Bn);
    conv2_sample_kernel<<<grid, 512, smemB>>>(pm25, w2, b2, wk, out);
}